// round 1
// baseline (speedup 1.0000x reference)
#include <cuda_runtime.h>
#include <math.h>

// Problem dims
#define D   768
#define H   12
#define SQ  256
#define BB  8
#define DH  64
#define M   (BB*SQ)     // 2048 rows
#define FF  (4*D)       // 3072
#define MD  ((size_t)M*D)

// ---------------- scratch (device globals; no allocs allowed) ----------------
__device__ float g_x[M*D];
__device__ float g_y[M*D];
__device__ float g_qkv[3*M*D];            // [3][B,H,S,DH]
__device__ float g_sc[(size_t)BB*H*SQ*SQ];// [B,H,S,S]
__device__ float g_h[M*D];                // attn/ffn2 output [B,S,D]
__device__ float g_ffn[(size_t)M*FF];     // ffn hidden

// ---------------- GEMM: C = A[M,K] @ W[K,N] + bias, 64x64x16 tiles ----------------
// mode: 0 = plain, 1 = GELU(exact), 2 = scatter to [B,H,S,DH] (requires N==768)
__global__ __launch_bounds__(256) void gemm_kernel(
    const float* __restrict__ A, const float* __restrict__ W,
    const float* __restrict__ bias, float* __restrict__ C,
    int N, int K, int mode)
{
    __shared__ float As[16][64];
    __shared__ float Bs[16][64];

    const int tid = threadIdx.x;
    const int tx = tid & 15, ty = tid >> 4;
    const int row0 = blockIdx.y * 64, col0 = blockIdx.x * 64;

    const int am = tid >> 2, ak = (tid & 3) * 4;   // A tile: 64 rows x 16 k
    const int bk = tid >> 4, bn = (tid & 15) * 4;  // B tile: 16 k x 64 cols

    float acc[4][4] = {};

    for (int k0 = 0; k0 < K; k0 += 16) {
        float4 av = *(const float4*)&A[(size_t)(row0 + am) * K + k0 + ak];
        As[ak + 0][am] = av.x;
        As[ak + 1][am] = av.y;
        As[ak + 2][am] = av.z;
        As[ak + 3][am] = av.w;
        *(float4*)&Bs[bk][bn] = *(const float4*)&W[(size_t)(k0 + bk) * N + col0 + bn];
        __syncthreads();

        #pragma unroll
        for (int kk = 0; kk < 16; kk++) {
            float4 a4 = *(float4*)&As[kk][ty * 4];
            float4 b4 = *(float4*)&Bs[kk][tx * 4];
            float ar[4] = {a4.x, a4.y, a4.z, a4.w};
            float br[4] = {b4.x, b4.y, b4.z, b4.w};
            #pragma unroll
            for (int i = 0; i < 4; i++)
                #pragma unroll
                for (int j = 0; j < 4; j++)
                    acc[i][j] += ar[i] * br[j];
        }
        __syncthreads();
    }

    #pragma unroll
    for (int i = 0; i < 4; i++) {
        int row = row0 + ty * 4 + i;
        #pragma unroll
        for (int j = 0; j < 4; j++) {
            int col = col0 + tx * 4 + j;
            float v = acc[i][j] + bias[col];
            if (mode == 1) {
                v = 0.5f * v * (1.0f + erff(v * 0.70710678118654752f));
                C[(size_t)row * N + col] = v;
            } else if (mode == 2) {
                int b_ = row >> 8, s = row & 255;
                int hh = col >> 6, dh = col & 63;
                C[(((size_t)b_ * H + hh) * SQ + s) * DH + dh] = v;
            } else {
                C[(size_t)row * N + col] = v;
            }
        }
    }
}

// ---------------- attention scores: Sc[b,h,q,k] = 0.125*Q.K - 10000*(1-mask) ----------------
__global__ __launch_bounds__(256) void scores_kernel(
    const float* __restrict__ Q, const float* __restrict__ Kk,
    const int* __restrict__ mask, float* __restrict__ Sc)
{
    __shared__ float qs[32][64];
    __shared__ float ks[64][68];  // [d][krow], padded

    const int bh = blockIdx.x;
    const int b = bh / H;
    const int q0 = blockIdx.y * 32;
    const int tid = threadIdx.x;

    const float* Qp = Q + ((size_t)bh * SQ + q0) * DH;
    for (int i = tid; i < 32 * 64; i += 256) qs[i >> 6][i & 63] = Qp[i];

    const int qi = tid >> 3, kj = (tid & 7) * 8;

    for (int kb = 0; kb < 4; kb++) {
        const float* Kp = Kk + ((size_t)bh * SQ + kb * 64) * DH;
        __syncthreads();
        for (int i = tid; i < 64 * 64; i += 256) ks[i & 63][i >> 6] = Kp[i];
        __syncthreads();

        float acc[8] = {};
        #pragma unroll
        for (int d = 0; d < 64; d++) {
            float qv = qs[qi][d];
            float4 k1 = *(float4*)&ks[d][kj];
            float4 k2 = *(float4*)&ks[d][kj + 4];
            acc[0] += qv * k1.x; acc[1] += qv * k1.y;
            acc[2] += qv * k1.z; acc[3] += qv * k1.w;
            acc[4] += qv * k2.x; acc[5] += qv * k2.y;
            acc[6] += qv * k2.z; acc[7] += qv * k2.w;
        }

        float* Sp = Sc + ((size_t)bh * SQ + (q0 + qi)) * SQ + kb * 64 + kj;
        #pragma unroll
        for (int j = 0; j < 8; j++) {
            float mv = (float)mask[b * SQ + kb * 64 + kj + j];
            Sp[j] = acc[j] * 0.125f - 10000.0f * (1.0f - mv);
        }
    }
}

// ---------------- softmax over last dim (256), one warp per row ----------------
__global__ __launch_bounds__(256) void softmax_kernel(float* __restrict__ Sc)
{
    const int row = blockIdx.x * 8 + (threadIdx.x >> 5);
    const int lane = threadIdx.x & 31;
    float* p = Sc + (size_t)row * SQ + lane * 8;

    float v[8];
    *(float4*)&v[0] = *(float4*)p;
    *(float4*)&v[4] = *(float4*)(p + 4);

    float m = v[0];
    #pragma unroll
    for (int j = 1; j < 8; j++) m = fmaxf(m, v[j]);
    #pragma unroll
    for (int o = 16; o; o >>= 1) m = fmaxf(m, __shfl_xor_sync(0xffffffffu, m, o));

    float s = 0.0f;
    #pragma unroll
    for (int j = 0; j < 8; j++) { v[j] = expf(v[j] - m); s += v[j]; }
    #pragma unroll
    for (int o = 16; o; o >>= 1) s += __shfl_xor_sync(0xffffffffu, s, o);

    float inv = 1.0f / s;
    #pragma unroll
    for (int j = 0; j < 8; j++) v[j] *= inv;

    *(float4*)p = *(float4*)&v[0];
    *(float4*)(p + 4) = *(float4*)&v[4];
}

// ---------------- PV: out[b,s, h*64+dh] = sum_k P[b,h,s,k] * V[b,h,k,dh] ----------------
__global__ __launch_bounds__(256) void pv_kernel(
    const float* __restrict__ P, const float* __restrict__ V,
    float* __restrict__ out)
{
    __shared__ float pt[64][68];  // [k][s], padded
    __shared__ float vs[64][64];  // [k][dh]

    const int bh = blockIdx.x;
    const int s0 = blockIdx.y * 64;
    const int b = bh / H, hh = bh % H;
    const int tid = threadIdx.x;
    const int tx = tid & 15, ty = tid >> 4;

    float acc[4][4] = {};

    for (int kb = 0; kb < 4; kb++) {
        const float* Pp = P + ((size_t)bh * SQ + s0) * SQ + kb * 64;
        const float* Vp = V + ((size_t)bh * SQ + kb * 64) * DH;
        __syncthreads();
        for (int i = tid; i < 4096; i += 256) {
            int si = i >> 6, kk = i & 63;
            pt[kk][si] = Pp[(size_t)si * SQ + kk];
        }
        for (int i = tid; i < 4096; i += 256) vs[i >> 6][i & 63] = Vp[i];
        __syncthreads();

        #pragma unroll
        for (int kk = 0; kk < 64; kk++) {
            float4 a4 = *(float4*)&pt[kk][ty * 4];
            float4 b4 = *(float4*)&vs[kk][tx * 4];
            float ar[4] = {a4.x, a4.y, a4.z, a4.w};
            float br[4] = {b4.x, b4.y, b4.z, b4.w};
            #pragma unroll
            for (int i = 0; i < 4; i++)
                #pragma unroll
                for (int j = 0; j < 4; j++)
                    acc[i][j] += ar[i] * br[j];
        }
    }

    #pragma unroll
    for (int i = 0; i < 4; i++) {
        int s = s0 + ty * 4 + i;
        #pragma unroll
        for (int j = 0; j < 4; j++) {
            int dh = tx * 4 + j;
            out[((size_t)b * SQ + s) * D + hh * DH + dh] = acc[i][j];
        }
    }
}

// ---------------- residual add + LayerNorm (in-place on x) ----------------
__global__ __launch_bounds__(256) void addln_kernel(
    float* __restrict__ x, const float* __restrict__ hbuf,
    const float* __restrict__ g, const float* __restrict__ bta)
{
    __shared__ float red[256];
    const int row = blockIdx.x;
    const size_t base = (size_t)row * D;
    const int t = threadIdx.x;

    float v0 = x[base + t]       + hbuf[base + t];
    float v1 = x[base + t + 256] + hbuf[base + t + 256];
    float v2 = x[base + t + 512] + hbuf[base + t + 512];

    red[t] = v0 + v1 + v2;
    __syncthreads();
    for (int o = 128; o; o >>= 1) { if (t < o) red[t] += red[t + o]; __syncthreads(); }
    float mean = red[0] * (1.0f / 768.0f);
    __syncthreads();

    float d0 = v0 - mean, d1 = v1 - mean, d2 = v2 - mean;
    red[t] = d0 * d0 + d1 * d1 + d2 * d2;
    __syncthreads();
    for (int o = 128; o; o >>= 1) { if (t < o) red[t] += red[t + o]; __syncthreads(); }
    float inv = rsqrtf(red[0] * (1.0f / 768.0f) + 1e-12f);

    x[base + t]       = d0 * inv * g[t]       + bta[t];
    x[base + t + 256] = d1 * inv * g[t + 256] + bta[t + 256];
    x[base + t + 512] = d2 * inv * g[t + 512] + bta[t + 512];
}

// ---------------- host orchestration ----------------
static void run_mhsa(const float* qin, const float* kvin,
                     const float* Wp, const float* bp, const int* mask,
                     float* stream_buf, const float* lng, const float* lnb,
                     float* qkv, float* sc, float* hbuf)
{
    dim3 gg(D / 64, M / 64);
    gemm_kernel<<<gg, 256>>>(qin,  Wp,             bp,         qkv,            D, D, 2);
    gemm_kernel<<<gg, 256>>>(kvin, Wp + (size_t)D*D,   bp + D,     qkv + MD,       D, D, 2);
    gemm_kernel<<<gg, 256>>>(kvin, Wp + (size_t)2*D*D, bp + 2*D,   qkv + 2*MD,     D, D, 2);
    scores_kernel<<<dim3(BB * H, SQ / 32), 256>>>(qkv, qkv + MD, mask, sc);
    softmax_kernel<<<BB * H * SQ / 8, 256>>>(sc);
    pv_kernel<<<dim3(BB * H, SQ / 64), 256>>>(sc, qkv + 2 * MD, hbuf);
    addln_kernel<<<M, 256>>>(stream_buf, hbuf, lng, lnb);
}

static void run_ffn(float* buf, const float* w1, const float* b1,
                    const float* w2, const float* b2,
                    const float* lng, const float* lnb,
                    float* ffn, float* hbuf)
{
    gemm_kernel<<<dim3(FF / 64, M / 64), 256>>>(buf, w1, b1, ffn, FF, D, 1);
    gemm_kernel<<<dim3(D / 64, M / 64), 256>>>(ffn, w2, b2, hbuf, D, FF, 0);
    addln_kernel<<<M, 256>>>(buf, hbuf, lng, lnb);
}

extern "C" void kernel_launch(void* const* d_in, const int* in_sizes, int n_in,
                              void* d_out, int out_size)
{
    const float* x     = (const float*)d_in[0];
    const float* y     = (const float*)d_in[1];
    const int*   xmask = (const int*)  d_in[2];
    const int*   ymask = (const int*)  d_in[3];
    const float* ax_w  = (const float*)d_in[4];
    const float* ax_b  = (const float*)d_in[5];
    const float* cx_w  = (const float*)d_in[6];
    const float* cx_b  = (const float*)d_in[7];
    const float* fx_w1 = (const float*)d_in[8];
    const float* fx_b1 = (const float*)d_in[9];
    const float* fx_w2 = (const float*)d_in[10];
    const float* fx_b2 = (const float*)d_in[11];
    const float* ay_w  = (const float*)d_in[12];
    const float* ay_b  = (const float*)d_in[13];
    const float* cy_w  = (const float*)d_in[14];
    const float* cy_b  = (const float*)d_in[15];
    const float* fy_w1 = (const float*)d_in[16];
    const float* fy_b1 = (const float*)d_in[17];
    const float* fy_w2 = (const float*)d_in[18];
    const float* fy_b2 = (const float*)d_in[19];
    const float* lnx_g = (const float*)d_in[20];
    const float* lnx_b = (const float*)d_in[21];
    const float* lny_g = (const float*)d_in[22];
    const float* lny_b = (const float*)d_in[23];

    float *gx, *gy, *gqkv, *gsc, *gh, *gffn;
    cudaGetSymbolAddress((void**)&gx,   g_x);
    cudaGetSymbolAddress((void**)&gy,   g_y);
    cudaGetSymbolAddress((void**)&gqkv, g_qkv);
    cudaGetSymbolAddress((void**)&gsc,  g_sc);
    cudaGetSymbolAddress((void**)&gh,   g_h);
    cudaGetSymbolAddress((void**)&gffn, g_ffn);

    cudaMemcpyAsync(gx, x, MD * sizeof(float), cudaMemcpyDeviceToDevice, 0);
    cudaMemcpyAsync(gy, y, MD * sizeof(float), cudaMemcpyDeviceToDevice, 0);

    for (int l = 0; l < 6; l++) {
        const float* axw = ax_w + (size_t)l * 3 * D * D;
        const float* axb = ax_b + (size_t)l * 3 * D;
        const float* ayw = ay_w + (size_t)l * 3 * D * D;
        const float* ayb = ay_b + (size_t)l * 3 * D;
        const float* cxw = cx_w + (size_t)l * 3 * D * D;
        const float* cxb = cx_b + (size_t)l * 3 * D;
        const float* cyw = cy_w + (size_t)l * 3 * D * D;
        const float* cyb = cy_b + (size_t)l * 3 * D;
        const float* fxw1 = fx_w1 + (size_t)l * D * FF;
        const float* fxb1 = fx_b1 + (size_t)l * FF;
        const float* fxw2 = fx_w2 + (size_t)l * FF * D;
        const float* fxb2 = fx_b2 + (size_t)l * D;
        const float* fyw1 = fy_w1 + (size_t)l * D * FF;
        const float* fyb1 = fy_b1 + (size_t)l * FF;
        const float* fyw2 = fy_w2 + (size_t)l * FF * D;
        const float* fyb2 = fy_b2 + (size_t)l * D;

        // self-attention x, self-attention y
        run_mhsa(gx, gx, axw, axb, xmask, gx, lnx_g + 0 * D, lnx_b + 0 * D, gqkv, gsc, gh);
        run_mhsa(gy, gy, ayw, ayb, ymask, gy, lny_g + 0 * D, lny_b + 0 * D, gqkv, gsc, gh);
        // cross x (q from x, kv from updated y), cross y (q from y, kv from updated x)
        run_mhsa(gx, gy, cxw, cxb, ymask, gx, lnx_g + 1 * D, lnx_b + 1 * D, gqkv, gsc, gh);
        run_mhsa(gy, gx, cyw, cyb, xmask, gy, lny_g + 1 * D, lny_b + 1 * D, gqkv, gsc, gh);
        // FFNs
        run_ffn(gx, fxw1, fxb1, fxw2, fxb2, lnx_g + 2 * D, lnx_b + 2 * D, gffn, gh);
        run_ffn(gy, fyw1, fyb1, fyw2, fyb2, lny_g + 2 * D, lny_b + 2 * D, gffn, gh);
    }

    cudaMemcpyAsync((float*)d_out,      gx, MD * sizeof(float), cudaMemcpyDeviceToDevice, 0);
    cudaMemcpyAsync((float*)d_out + MD, gy, MD * sizeof(float), cudaMemcpyDeviceToDevice, 0);
}

// round 3
// speedup vs baseline: 2.8471x; 2.8471x over previous
#include <cuda_runtime.h>
#include <math.h>
#include <stdint.h>

// Problem dims
#define D   768
#define H   12
#define SQ  256
#define BB  8
#define DH  64
#define M   (BB*SQ)     // 2048 rows
#define FF  (4*D)       // 3072
#define MD  ((size_t)M*D)

// ---------------- scratch (device globals; no allocs allowed) ----------------
__device__ float g_x[M*D];
__device__ float g_y[M*D];
__device__ float g_qkv[3*M*D];            // [3][B,H,S,DH]
__device__ float g_sc[(size_t)BB*H*SQ*SQ];// [B,H,S,S]
__device__ float g_h[M*D];                // attn/ffn2 output [B,S,D]
__device__ float g_ffn[(size_t)M*FF];     // ffn hidden

// ---------------- tf32 helpers ----------------
__device__ __forceinline__ float to_tf32(float x) {
    float r;
    asm("cvt.rna.tf32.f32 %0, %1;" : "=f"(r) : "f"(x));
    return r;
}

__device__ __forceinline__ void mma8(float c[4],
    uint32_t a0, uint32_t a1, uint32_t a2, uint32_t a3,
    uint32_t b0, uint32_t b1)
{
    asm volatile(
        "mma.sync.aligned.m16n8k8.row.col.f32.tf32.tf32.f32 "
        "{%0,%1,%2,%3}, {%4,%5,%6,%7}, {%8,%9}, {%0,%1,%2,%3};"
        : "+f"(c[0]), "+f"(c[1]), "+f"(c[2]), "+f"(c[3])
        : "r"(a0), "r"(a1), "r"(a2), "r"(a3), "r"(b0), "r"(b1));
}

__device__ __forceinline__ float gelu_exact(float v) {
    return 0.5f * v * (1.0f + erff(v * 0.70710678118654752f));
}

// ---------------- GEMM: C = A[M,K] @ W[K,N] + bias, tf32 mma ----------------
// Block tile 128x64, 8 warps (4m x 2n), warp tile 32x32, BK=32.
// mode: 0 = plain, 1 = GELU(exact), 2 = scatter to [B,H,S,DH] (N==768)
__global__ __launch_bounds__(256) void gemm_tf32(
    const float* __restrict__ A, const float* __restrict__ W,
    const float* __restrict__ bias, float* __restrict__ C,
    int N, int K, int mode)
{
    __shared__ float As[128][36];   // [m][k], pad 4
    __shared__ float Bs[32][72];    // [k][n], pad 8

    const int tid = threadIdx.x;
    const int lane = tid & 31, warp = tid >> 5;
    const int wm = warp >> 1, wn = warp & 1;
    const int g = lane >> 2, tg = lane & 3;
    const int row0 = blockIdx.y * 128, col0 = blockIdx.x * 64;

    float acc[2][4][4] = {};

    for (int k0 = 0; k0 < K; k0 += 32) {
        #pragma unroll
        for (int i = 0; i < 4; i++) {
            int f = tid + 256 * i;
            int r = f >> 3, c4 = (f & 7) << 2;
            float4 v = *(const float4*)&A[(size_t)(row0 + r) * K + k0 + c4];
            float4 t;
            t.x = to_tf32(v.x); t.y = to_tf32(v.y);
            t.z = to_tf32(v.z); t.w = to_tf32(v.w);
            *(float4*)&As[r][c4] = t;
        }
        #pragma unroll
        for (int i = 0; i < 2; i++) {
            int f = tid + 256 * i;
            int r = f >> 4, c4 = (f & 15) << 2;
            float4 v = *(const float4*)&W[(size_t)(k0 + r) * N + col0 + c4];
            float4 t;
            t.x = to_tf32(v.x); t.y = to_tf32(v.y);
            t.z = to_tf32(v.z); t.w = to_tf32(v.w);
            *(float4*)&Bs[r][c4] = t;
        }
        __syncthreads();

        #pragma unroll
        for (int ks = 0; ks < 4; ks++) {
            const int k8 = ks * 8;
            uint32_t a[2][4], b[4][2];
            #pragma unroll
            for (int mf = 0; mf < 2; mf++) {
                int m0 = wm * 32 + mf * 16 + g;
                a[mf][0] = __float_as_uint(As[m0][k8 + tg]);
                a[mf][1] = __float_as_uint(As[m0 + 8][k8 + tg]);
                a[mf][2] = __float_as_uint(As[m0][k8 + tg + 4]);
                a[mf][3] = __float_as_uint(As[m0 + 8][k8 + tg + 4]);
            }
            #pragma unroll
            for (int nf = 0; nf < 4; nf++) {
                int n0 = wn * 32 + nf * 8 + g;
                b[nf][0] = __float_as_uint(Bs[k8 + tg][n0]);
                b[nf][1] = __float_as_uint(Bs[k8 + tg + 4][n0]);
            }
            #pragma unroll
            for (int mf = 0; mf < 2; mf++)
                #pragma unroll
                for (int nf = 0; nf < 4; nf++)
                    mma8(acc[mf][nf], a[mf][0], a[mf][1], a[mf][2], a[mf][3],
                         b[nf][0], b[nf][1]);
        }
        __syncthreads();
    }

    #pragma unroll
    for (int mf = 0; mf < 2; mf++) {
        int r_lo = row0 + wm * 32 + mf * 16 + g;
        #pragma unroll
        for (int nf = 0; nf < 4; nf++) {
            int c = col0 + wn * 32 + nf * 8 + tg * 2;
            float b0 = bias[c], b1 = bias[c + 1];
            float v00 = acc[mf][nf][0] + b0, v01 = acc[mf][nf][1] + b1;
            float v10 = acc[mf][nf][2] + b0, v11 = acc[mf][nf][3] + b1;
            if (mode == 1) {
                v00 = gelu_exact(v00); v01 = gelu_exact(v01);
                v10 = gelu_exact(v10); v11 = gelu_exact(v11);
            }
            if (mode == 2) {
                int hh = c >> 6, dh = c & 63;
                int b_0 = r_lo >> 8, s_0 = r_lo & 255;
                int b_1 = (r_lo + 8) >> 8, s_1 = (r_lo + 8) & 255;
                *(float2*)&C[(((size_t)b_0 * H + hh) * SQ + s_0) * DH + dh] = make_float2(v00, v01);
                *(float2*)&C[(((size_t)b_1 * H + hh) * SQ + s_1) * DH + dh] = make_float2(v10, v11);
            } else {
                *(float2*)&C[(size_t)r_lo * N + c] = make_float2(v00, v01);
                *(float2*)&C[(size_t)(r_lo + 8) * N + c] = make_float2(v10, v11);
            }
        }
    }
}

// ---------------- scores: Sc[b,h,q,k] = 0.125*Q.K^T - 10000*(1-mask) ----------------
// Block: 128(q) x 64(kpos), contraction DH=64 in two BK=32 chunks.
__global__ __launch_bounds__(256) void scores_tf32(
    const float* __restrict__ Q, const float* __restrict__ Kk,
    const int* __restrict__ mask, float* __restrict__ Sc)
{
    __shared__ float As[128][36];   // [q][d-chunk]
    __shared__ float Ks[64][68];    // [kpos][d] full

    const int tid = threadIdx.x;
    const int lane = tid & 31, warp = tid >> 5;
    const int wm = warp >> 1, wn = warp & 1;
    const int g = lane >> 2, tg = lane & 3;

    const int bh = blockIdx.x;
    const int b = bh / H;
    const int q0 = blockIdx.y * 128;
    const int n0base = blockIdx.z * 64;

    const float* Qp = Q + ((size_t)bh * SQ + q0) * DH;
    const float* Kp = Kk + ((size_t)bh * SQ + n0base) * DH;

    // Load full K tile [64 kpos][64 d], row-major, coalesced.
    #pragma unroll
    for (int i = 0; i < 4; i++) {
        int f = tid + 256 * i;
        int n = f >> 4, d4 = (f & 15) << 2;
        float4 v = *(const float4*)&Kp[(size_t)n * DH + d4];
        float4 t;
        t.x = to_tf32(v.x); t.y = to_tf32(v.y);
        t.z = to_tf32(v.z); t.w = to_tf32(v.w);
        *(float4*)&Ks[n][d4] = t;
    }

    float acc[2][4][4] = {};

    for (int kb = 0; kb < 64; kb += 32) {
        #pragma unroll
        for (int i = 0; i < 4; i++) {
            int f = tid + 256 * i;
            int r = f >> 3, c4 = (f & 7) << 2;
            float4 v = *(const float4*)&Qp[(size_t)r * DH + kb + c4];
            float4 t;
            t.x = to_tf32(v.x); t.y = to_tf32(v.y);
            t.z = to_tf32(v.z); t.w = to_tf32(v.w);
            *(float4*)&As[r][c4] = t;
        }
        __syncthreads();

        #pragma unroll
        for (int ks = 0; ks < 4; ks++) {
            const int k8 = ks * 8;
            uint32_t a[2][4], bfr[4][2];
            #pragma unroll
            for (int mf = 0; mf < 2; mf++) {
                int m0 = wm * 32 + mf * 16 + g;
                a[mf][0] = __float_as_uint(As[m0][k8 + tg]);
                a[mf][1] = __float_as_uint(As[m0 + 8][k8 + tg]);
                a[mf][2] = __float_as_uint(As[m0][k8 + tg + 4]);
                a[mf][3] = __float_as_uint(As[m0 + 8][k8 + tg + 4]);
            }
            #pragma unroll
            for (int nf = 0; nf < 4; nf++) {
                int n0 = wn * 32 + nf * 8 + g;
                bfr[nf][0] = __float_as_uint(Ks[n0][kb + k8 + tg]);
                bfr[nf][1] = __float_as_uint(Ks[n0][kb + k8 + tg + 4]);
            }
            #pragma unroll
            for (int mf = 0; mf < 2; mf++)
                #pragma unroll
                for (int nf = 0; nf < 4; nf++)
                    mma8(acc[mf][nf], a[mf][0], a[mf][1], a[mf][2], a[mf][3],
                         bfr[nf][0], bfr[nf][1]);
        }
        __syncthreads();
    }

    #pragma unroll
    for (int mf = 0; mf < 2; mf++) {
        int rq = q0 + wm * 32 + mf * 16 + g;
        #pragma unroll
        for (int nf = 0; nf < 4; nf++) {
            int kk = n0base + wn * 32 + nf * 8 + tg * 2;
            float p0 = 10000.0f * (1.0f - (float)mask[b * SQ + kk]);
            float p1 = 10000.0f * (1.0f - (float)mask[b * SQ + kk + 1]);
            float v00 = acc[mf][nf][0] * 0.125f - p0;
            float v01 = acc[mf][nf][1] * 0.125f - p1;
            float v10 = acc[mf][nf][2] * 0.125f - p0;
            float v11 = acc[mf][nf][3] * 0.125f - p1;
            *(float2*)&Sc[((size_t)bh * SQ + rq) * SQ + kk] = make_float2(v00, v01);
            *(float2*)&Sc[((size_t)bh * SQ + rq + 8) * SQ + kk] = make_float2(v10, v11);
        }
    }
}

// ---------------- PV: out[b,s,h*64+dh] = P[b,h,s,:] @ V[b,h,:,dh] ----------------
// Block: 128(s) x 64(dh), contraction 256 in BK=32 chunks.
__global__ __launch_bounds__(256) void pv_tf32(
    const float* __restrict__ P, const float* __restrict__ V,
    float* __restrict__ out)
{
    __shared__ float As[128][36];
    __shared__ float Bs[32][72];

    const int tid = threadIdx.x;
    const int lane = tid & 31, warp = tid >> 5;
    const int wm = warp >> 1, wn = warp & 1;
    const int g = lane >> 2, tg = lane & 3;

    const int bh = blockIdx.x;
    const int s0 = blockIdx.y * 128;
    const int b = bh / H, hh = bh % H;

    const float* Pp = P + ((size_t)bh * SQ + s0) * SQ;
    const float* Vp = V + (size_t)bh * SQ * DH;

    float acc[2][4][4] = {};

    for (int k0 = 0; k0 < SQ; k0 += 32) {
        #pragma unroll
        for (int i = 0; i < 4; i++) {
            int f = tid + 256 * i;
            int r = f >> 3, c4 = (f & 7) << 2;
            float4 v = *(const float4*)&Pp[(size_t)r * SQ + k0 + c4];
            float4 t;
            t.x = to_tf32(v.x); t.y = to_tf32(v.y);
            t.z = to_tf32(v.z); t.w = to_tf32(v.w);
            *(float4*)&As[r][c4] = t;
        }
        #pragma unroll
        for (int i = 0; i < 2; i++) {
            int f = tid + 256 * i;
            int r = f >> 4, c4 = (f & 15) << 2;
            float4 v = *(const float4*)&Vp[(size_t)(k0 + r) * DH + c4];
            float4 t;
            t.x = to_tf32(v.x); t.y = to_tf32(v.y);
            t.z = to_tf32(v.z); t.w = to_tf32(v.w);
            *(float4*)&Bs[r][c4] = t;
        }
        __syncthreads();

        #pragma unroll
        for (int ks = 0; ks < 4; ks++) {
            const int k8 = ks * 8;
            uint32_t a[2][4], bfr[4][2];
            #pragma unroll
            for (int mf = 0; mf < 2; mf++) {
                int m0 = wm * 32 + mf * 16 + g;
                a[mf][0] = __float_as_uint(As[m0][k8 + tg]);
                a[mf][1] = __float_as_uint(As[m0 + 8][k8 + tg]);
                a[mf][2] = __float_as_uint(As[m0][k8 + tg + 4]);
                a[mf][3] = __float_as_uint(As[m0 + 8][k8 + tg + 4]);
            }
            #pragma unroll
            for (int nf = 0; nf < 4; nf++) {
                int n0 = wn * 32 + nf * 8 + g;
                bfr[nf][0] = __float_as_uint(Bs[k8 + tg][n0]);
                bfr[nf][1] = __float_as_uint(Bs[k8 + tg + 4][n0]);
            }
            #pragma unroll
            for (int mf = 0; mf < 2; mf++)
                #pragma unroll
                for (int nf = 0; nf < 4; nf++)
                    mma8(acc[mf][nf], a[mf][0], a[mf][1], a[mf][2], a[mf][3],
                         bfr[nf][0], bfr[nf][1]);
        }
        __syncthreads();
    }

    #pragma unroll
    for (int mf = 0; mf < 2; mf++) {
        int s = s0 + wm * 32 + mf * 16 + g;
        #pragma unroll
        for (int nf = 0; nf < 4; nf++) {
            int c = hh * DH + wn * 32 + nf * 8 + tg * 2;
            *(float2*)&out[((size_t)b * SQ + s) * D + c] =
                make_float2(acc[mf][nf][0], acc[mf][nf][1]);
            *(float2*)&out[((size_t)b * SQ + s + 8) * D + c] =
                make_float2(acc[mf][nf][2], acc[mf][nf][3]);
        }
    }
}

// ---------------- softmax over last dim (256), one warp per row ----------------
__global__ __launch_bounds__(256) void softmax_kernel(float* __restrict__ Sc)
{
    const int row = blockIdx.x * 8 + (threadIdx.x >> 5);
    const int lane = threadIdx.x & 31;
    float* p = Sc + (size_t)row * SQ + lane * 8;

    float v[8];
    *(float4*)&v[0] = *(float4*)p;
    *(float4*)&v[4] = *(float4*)(p + 4);

    float m = v[0];
    #pragma unroll
    for (int j = 1; j < 8; j++) m = fmaxf(m, v[j]);
    #pragma unroll
    for (int o = 16; o; o >>= 1) m = fmaxf(m, __shfl_xor_sync(0xffffffffu, m, o));

    float s = 0.0f;
    #pragma unroll
    for (int j = 0; j < 8; j++) { v[j] = expf(v[j] - m); s += v[j]; }
    #pragma unroll
    for (int o = 16; o; o >>= 1) s += __shfl_xor_sync(0xffffffffu, s, o);

    float inv = 1.0f / s;
    #pragma unroll
    for (int j = 0; j < 8; j++) v[j] *= inv;

    *(float4*)p = *(float4*)&v[0];
    *(float4*)(p + 4) = *(float4*)&v[4];
}

// ---------------- residual add + LayerNorm (in-place on x) ----------------
__global__ __launch_bounds__(256) void addln_kernel(
    float* __restrict__ x, const float* __restrict__ hbuf,
    const float* __restrict__ g, const float* __restrict__ bta)
{
    __shared__ float red[256];
    const int row = blockIdx.x;
    const size_t base = (size_t)row * D;
    const int t = threadIdx.x;

    float v0 = x[base + t]       + hbuf[base + t];
    float v1 = x[base + t + 256] + hbuf[base + t + 256];
    float v2 = x[base + t + 512] + hbuf[base + t + 512];

    red[t] = v0 + v1 + v2;
    __syncthreads();
    for (int o = 128; o; o >>= 1) { if (t < o) red[t] += red[t + o]; __syncthreads(); }
    float mean = red[0] * (1.0f / 768.0f);
    __syncthreads();

    float d0 = v0 - mean, d1 = v1 - mean, d2 = v2 - mean;
    red[t] = d0 * d0 + d1 * d1 + d2 * d2;
    __syncthreads();
    for (int o = 128; o; o >>= 1) { if (t < o) red[t] += red[t + o]; __syncthreads(); }
    float inv = rsqrtf(red[0] * (1.0f / 768.0f) + 1e-12f);

    x[base + t]       = d0 * inv * g[t]       + bta[t];
    x[base + t + 256] = d1 * inv * g[t + 256] + bta[t + 256];
    x[base + t + 512] = d2 * inv * g[t + 512] + bta[t + 512];
}

// ---------------- host orchestration ----------------
static float *gx, *gy, *gqkv, *gsc, *gh, *gffn;
static bool g_resolved = false;

static void resolve_symbols() {
    if (g_resolved) return;
    cudaGetSymbolAddress((void**)&gx,   g_x);
    cudaGetSymbolAddress((void**)&gy,   g_y);
    cudaGetSymbolAddress((void**)&gqkv, g_qkv);
    cudaGetSymbolAddress((void**)&gsc,  g_sc);
    cudaGetSymbolAddress((void**)&gh,   g_h);
    cudaGetSymbolAddress((void**)&gffn, g_ffn);
    g_resolved = true;
}

static void run_mhsa(const float* qin, const float* kvin,
                     const float* Wp, const float* bp, const int* mask,
                     float* stream_buf, const float* lng, const float* lnb)
{
    dim3 gg(D / 64, M / 128);
    gemm_tf32<<<gg, 256>>>(qin,  Wp,                 bp,       gqkv,          D, D, 2);
    gemm_tf32<<<gg, 256>>>(kvin, Wp + (size_t)D*D,   bp + D,   gqkv + MD,     D, D, 2);
    gemm_tf32<<<gg, 256>>>(kvin, Wp + (size_t)2*D*D, bp + 2*D, gqkv + 2*MD,   D, D, 2);
    scores_tf32<<<dim3(BB * H, SQ / 128, SQ / 64), 256>>>(gqkv, gqkv + MD, mask, gsc);
    softmax_kernel<<<BB * H * SQ / 8, 256>>>(gsc);
    pv_tf32<<<dim3(BB * H, SQ / 128), 256>>>(gsc, gqkv + 2 * MD, gh);
    addln_kernel<<<M, 256>>>(stream_buf, gh, lng, lnb);
}

static void run_ffn(float* buf, const float* w1, const float* b1,
                    const float* w2, const float* b2,
                    const float* lng, const float* lnb)
{
    gemm_tf32<<<dim3(FF / 64, M / 128), 256>>>(buf, w1, b1, gffn, FF, D, 1);
    gemm_tf32<<<dim3(D / 64, M / 128), 256>>>(gffn, w2, b2, gh, D, FF, 0);
    addln_kernel<<<M, 256>>>(buf, gh, lng, lnb);
}

extern "C" void kernel_launch(void* const* d_in, const int* in_sizes, int n_in,
                              void* d_out, int out_size)
{
    const float* x     = (const float*)d_in[0];
    const float* y     = (const float*)d_in[1];
    const int*   xmask = (const int*)  d_in[2];
    const int*   ymask = (const int*)  d_in[3];
    const float* ax_w  = (const float*)d_in[4];
    const float* ax_b  = (const float*)d_in[5];
    const float* cx_w  = (const float*)d_in[6];
    const float* cx_b  = (const float*)d_in[7];
    const float* fx_w1 = (const float*)d_in[8];
    const float* fx_b1 = (const float*)d_in[9];
    const float* fx_w2 = (const float*)d_in[10];
    const float* fx_b2 = (const float*)d_in[11];
    const float* ay_w  = (const float*)d_in[12];
    const float* ay_b  = (const float*)d_in[13];
    const float* cy_w  = (const float*)d_in[14];
    const float* cy_b  = (const float*)d_in[15];
    const float* fy_w1 = (const float*)d_in[16];
    const float* fy_b1 = (const float*)d_in[17];
    const float* fy_w2 = (const float*)d_in[18];
    const float* fy_b2 = (const float*)d_in[19];
    const float* lnx_g = (const float*)d_in[20];
    const float* lnx_b = (const float*)d_in[21];
    const float* lny_g = (const float*)d_in[22];
    const float* lny_b = (const float*)d_in[23];

    resolve_symbols();

    cudaMemcpyAsync(gx, x, MD * sizeof(float), cudaMemcpyDeviceToDevice, 0);
    cudaMemcpyAsync(gy, y, MD * sizeof(float), cudaMemcpyDeviceToDevice, 0);

    for (int l = 0; l < 6; l++) {
        const float* axw = ax_w + (size_t)l * 3 * D * D;
        const float* axb = ax_b + (size_t)l * 3 * D;
        const float* ayw = ay_w + (size_t)l * 3 * D * D;
        const float* ayb = ay_b + (size_t)l * 3 * D;
        const float* cxw = cx_w + (size_t)l * 3 * D * D;
        const float* cxb = cx_b + (size_t)l * 3 * D;
        const float* cyw = cy_w + (size_t)l * 3 * D * D;
        const float* cyb = cy_b + (size_t)l * 3 * D;
        const float* fxw1 = fx_w1 + (size_t)l * D * FF;
        const float* fxb1 = fx_b1 + (size_t)l * FF;
        const float* fxw2 = fx_w2 + (size_t)l * FF * D;
        const float* fxb2 = fx_b2 + (size_t)l * D;
        const float* fyw1 = fy_w1 + (size_t)l * D * FF;
        const float* fyb1 = fy_b1 + (size_t)l * FF;
        const float* fyw2 = fy_w2 + (size_t)l * FF * D;
        const float* fyb2 = fy_b2 + (size_t)l * D;

        run_mhsa(gx, gx, axw, axb, xmask, gx, lnx_g + 0 * D, lnx_b + 0 * D);
        run_mhsa(gy, gy, ayw, ayb, ymask, gy, lny_g + 0 * D, lny_b + 0 * D);
        run_mhsa(gx, gy, cxw, cxb, ymask, gx, lnx_g + 1 * D, lnx_b + 1 * D);
        run_mhsa(gy, gx, cyw, cyb, xmask, gy, lny_g + 1 * D, lny_b + 1 * D);
        run_ffn(gx, fxw1, fxb1, fxw2, fxb2, lnx_g + 2 * D, lnx_b + 2 * D);
        run_ffn(gy, fyw1, fyb1, fyw2, fyb2, lny_g + 2 * D, lny_b + 2 * D);
    }

    cudaMemcpyAsync((float*)d_out,      gx, MD * sizeof(float), cudaMemcpyDeviceToDevice, 0);
    cudaMemcpyAsync((float*)d_out + MD, gy, MD * sizeof(float), cudaMemcpyDeviceToDevice, 0);
}

// round 4
// speedup vs baseline: 3.6322x; 1.2758x over previous
#include <cuda_runtime.h>
#include <math.h>
#include <stdint.h>

// Problem dims
#define D   768
#define H   12
#define SQ  256
#define BB  8
#define DH  64
#define M   (BB*SQ)     // 2048 rows
#define FF  (4*D)       // 3072
#define MD  ((size_t)M*D)

// ---------------- scratch (device globals; no allocs allowed) ----------------
__device__ float g_x[M*D];
__device__ float g_y[M*D];
__device__ float g_qkv[3*M*D];            // [3][B,H,S,DH]
__device__ float g_sc[(size_t)BB*H*SQ*SQ];// [B,H,S,S]
__device__ float g_h[M*D];                // attn/ffn2 output [B,S,D]
__device__ float g_ffn[(size_t)M*FF];     // ffn hidden

// ---------------- tf32 helpers ----------------
__device__ __forceinline__ float to_tf32(float x) {
    float r;
    asm("cvt.rna.tf32.f32 %0, %1;" : "=f"(r) : "f"(x));
    return r;
}

__device__ __forceinline__ void mma8(float c[4],
    uint32_t a0, uint32_t a1, uint32_t a2, uint32_t a3,
    uint32_t b0, uint32_t b1)
{
    asm volatile(
        "mma.sync.aligned.m16n8k8.row.col.f32.tf32.tf32.f32 "
        "{%0,%1,%2,%3}, {%4,%5,%6,%7}, {%8,%9}, {%0,%1,%2,%3};"
        : "+f"(c[0]), "+f"(c[1]), "+f"(c[2]), "+f"(c[3])
        : "r"(a0), "r"(a1), "r"(a2), "r"(a3), "r"(b0), "r"(b1));
}

__device__ __forceinline__ float gelu_exact(float v) {
    return 0.5f * v * (1.0f + erff(v * 0.70710678118654752f));
}

// ============================================================================
// Double-buffered tf32 GEMM.  Block tile 128 x BN, BK=32, 256 threads,
// 8 warps as 2(m) x 4(n):  warp tile 64 x (BN/4).
// MODE: 0 = plain+bias, 1 = bias+GELU, 2 = QKV fused: N is per-matrix (768),
//       grid.x spans nmats*768/BN blocks; matrix selection per block, A is
//       Aq for matrix 0 and Akv for matrices 1,2; C scatters to [mat][B,H,S,DH].
// ============================================================================
template<int BN, int MODE>
__global__ __launch_bounds__(256) void gemm_db(
    const float* __restrict__ Aq, const float* __restrict__ Akv,
    const float* __restrict__ W, const float* __restrict__ bias,
    float* __restrict__ C, int N, int K)
{
    constexpr int BP = BN + 8;            // B smem row stride (floats)
    constexpr int NF = BN / 32;           // b-fragments per warp (4 or 2)
    constexpr int WN = BN / 4;            // warp n-tile
    constexpr int NB4 = (32 * BN / 4) / 256; // B float4 loads per thread (4 or 2)
    constexpr int ASZ = 128 * 36;         // one A buffer (floats)
    constexpr int BSZ = 32 * BP;          // one B buffer (floats)

    extern __shared__ float smem[];
    float* sA = smem;            // [2][128][36]
    float* sB = smem + 2 * ASZ;  // [2][32][BP]

    const int tid = threadIdx.x;
    const int lane = tid & 31, warp = tid >> 5;
    const int wm = warp >> 2, wn = warp & 3;     // 2 x 4 warps
    const int g = lane >> 2, tg = lane & 3;
    const int row0 = blockIdx.y * 128;

    const float* A; const float* Wp; const float* bp; float* Cp; int col0;
    if (MODE == 2) {
        const int perMat = 768 / BN;
        const int mat = blockIdx.x / perMat;
        col0 = (blockIdx.x % perMat) * BN;
        A  = (mat == 0) ? Aq : Akv;
        Wp = W + (size_t)mat * D * D;
        bp = bias + mat * D;
        Cp = C + (size_t)mat * MD;
    } else {
        col0 = blockIdx.x * BN;
        A = Aq; Wp = W; bp = bias; Cp = C;
    }

    float acc[4][NF][4] = {};
    float4 ar[4], br[NB4];

    // ---- load helpers (as lambdas via macros) ----
    #define LOAD_A(K0) { \
        _Pragma("unroll") \
        for (int j = 0; j < 4; j++) { \
            int f = tid + 256 * j; \
            int r = f >> 3, c4 = (f & 7) << 2; \
            ar[j] = *(const float4*)&A[(size_t)(row0 + r) * K + (K0) + c4]; \
        } }
    #define LOAD_B(K0) { \
        _Pragma("unroll") \
        for (int j = 0; j < NB4; j++) { \
            int f = tid + 256 * j; \
            int r = f / (BN / 4), c4 = (f % (BN / 4)) << 2; \
            br[j] = *(const float4*)&Wp[(size_t)((K0) + r) * N + col0 + c4]; \
        } }
    #define STS_AB(BUF) { \
        _Pragma("unroll") \
        for (int j = 0; j < 4; j++) { \
            int f = tid + 256 * j; \
            int r = f >> 3, c4 = (f & 7) << 2; \
            float* p = &sA[(BUF) * ASZ + r * 36 + c4]; \
            p[0] = to_tf32(ar[j].x); p[1] = to_tf32(ar[j].y); \
            p[2] = to_tf32(ar[j].z); p[3] = to_tf32(ar[j].w); \
        } \
        _Pragma("unroll") \
        for (int j = 0; j < NB4; j++) { \
            int f = tid + 256 * j; \
            int r = f / (BN / 4), c4 = (f % (BN / 4)) << 2; \
            float* p = &sB[(BUF) * BSZ + r * BP + c4]; \
            p[0] = to_tf32(br[j].x); p[1] = to_tf32(br[j].y); \
            p[2] = to_tf32(br[j].z); p[3] = to_tf32(br[j].w); \
        } }

    LOAD_A(0); LOAD_B(0);
    STS_AB(0);
    __syncthreads();

    int buf = 0;
    for (int k0 = 0; k0 < K; k0 += 32) {
        const bool more = (k0 + 32 < K);
        if (more) { LOAD_A(k0 + 32); LOAD_B(k0 + 32); }

        const float* cA = &sA[buf * ASZ];
        const float* cB = &sB[buf * BSZ];
        #pragma unroll
        for (int ks = 0; ks < 4; ks++) {
            const int k8 = ks * 8;
            uint32_t a[4][4], b[NF][2];
            #pragma unroll
            for (int mf = 0; mf < 4; mf++) {
                int m0 = wm * 64 + mf * 16 + g;
                a[mf][0] = __float_as_uint(cA[m0 * 36 + k8 + tg]);
                a[mf][1] = __float_as_uint(cA[(m0 + 8) * 36 + k8 + tg]);
                a[mf][2] = __float_as_uint(cA[m0 * 36 + k8 + tg + 4]);
                a[mf][3] = __float_as_uint(cA[(m0 + 8) * 36 + k8 + tg + 4]);
            }
            #pragma unroll
            for (int nf = 0; nf < NF; nf++) {
                int n0 = wn * WN + nf * 8 + g;
                b[nf][0] = __float_as_uint(cB[(k8 + tg) * BP + n0]);
                b[nf][1] = __float_as_uint(cB[(k8 + tg + 4) * BP + n0]);
            }
            #pragma unroll
            for (int mf = 0; mf < 4; mf++)
                #pragma unroll
                for (int nf = 0; nf < NF; nf++)
                    mma8(acc[mf][nf], a[mf][0], a[mf][1], a[mf][2], a[mf][3],
                         b[nf][0], b[nf][1]);
        }

        if (more) {
            STS_AB(buf ^ 1);
            __syncthreads();
            buf ^= 1;
        }
    }

    #undef LOAD_A
    #undef LOAD_B
    #undef STS_AB

    // ---- epilogue ----
    #pragma unroll
    for (int mf = 0; mf < 4; mf++) {
        int r_lo = row0 + wm * 64 + mf * 16 + g;
        #pragma unroll
        for (int nf = 0; nf < NF; nf++) {
            int c = col0 + wn * WN + nf * 8 + tg * 2;
            float b0 = bp[c], b1 = bp[c + 1];
            float v00 = acc[mf][nf][0] + b0, v01 = acc[mf][nf][1] + b1;
            float v10 = acc[mf][nf][2] + b0, v11 = acc[mf][nf][3] + b1;
            if (MODE == 1) {
                v00 = gelu_exact(v00); v01 = gelu_exact(v01);
                v10 = gelu_exact(v10); v11 = gelu_exact(v11);
            }
            if (MODE == 2) {
                int hh = c >> 6, dh = c & 63;
                int b_0 = r_lo >> 8, s_0 = r_lo & 255;
                int b_1 = (r_lo + 8) >> 8, s_1 = (r_lo + 8) & 255;
                *(float2*)&Cp[(((size_t)b_0 * H + hh) * SQ + s_0) * DH + dh] = make_float2(v00, v01);
                *(float2*)&Cp[(((size_t)b_1 * H + hh) * SQ + s_1) * DH + dh] = make_float2(v10, v11);
            } else {
                *(float2*)&Cp[(size_t)r_lo * N + c] = make_float2(v00, v01);
                *(float2*)&Cp[(size_t)(r_lo + 8) * N + c] = make_float2(v10, v11);
            }
        }
    }
}

// ---------------- scores: Sc[b,h,q,k] = 0.125*Q.K^T - 10000*(1-mask) ----------------
__global__ __launch_bounds__(256) void scores_tf32(
    const float* __restrict__ Q, const float* __restrict__ Kk,
    const int* __restrict__ mask, float* __restrict__ Sc)
{
    __shared__ float As[128][36];
    __shared__ float Ks[64][68];

    const int tid = threadIdx.x;
    const int lane = tid & 31, warp = tid >> 5;
    const int wm = warp >> 1, wn = warp & 1;
    const int g = lane >> 2, tg = lane & 3;

    const int bh = blockIdx.x;
    const int b = bh / H;
    const int q0 = blockIdx.y * 128;
    const int n0base = blockIdx.z * 64;

    const float* Qp = Q + ((size_t)bh * SQ + q0) * DH;
    const float* Kp = Kk + ((size_t)bh * SQ + n0base) * DH;

    #pragma unroll
    for (int i = 0; i < 4; i++) {
        int f = tid + 256 * i;
        int n = f >> 4, d4 = (f & 15) << 2;
        float4 v = *(const float4*)&Kp[(size_t)n * DH + d4];
        float4 t;
        t.x = to_tf32(v.x); t.y = to_tf32(v.y);
        t.z = to_tf32(v.z); t.w = to_tf32(v.w);
        *(float4*)&Ks[n][d4] = t;
    }

    float acc[2][4][4] = {};

    for (int kb = 0; kb < 64; kb += 32) {
        #pragma unroll
        for (int i = 0; i < 4; i++) {
            int f = tid + 256 * i;
            int r = f >> 3, c4 = (f & 7) << 2;
            float4 v = *(const float4*)&Qp[(size_t)r * DH + kb + c4];
            float4 t;
            t.x = to_tf32(v.x); t.y = to_tf32(v.y);
            t.z = to_tf32(v.z); t.w = to_tf32(v.w);
            *(float4*)&As[r][c4] = t;
        }
        __syncthreads();

        #pragma unroll
        for (int ks = 0; ks < 4; ks++) {
            const int k8 = ks * 8;
            uint32_t a[2][4], bfr[4][2];
            #pragma unroll
            for (int mf = 0; mf < 2; mf++) {
                int m0 = wm * 32 + mf * 16 + g;
                a[mf][0] = __float_as_uint(As[m0][k8 + tg]);
                a[mf][1] = __float_as_uint(As[m0 + 8][k8 + tg]);
                a[mf][2] = __float_as_uint(As[m0][k8 + tg + 4]);
                a[mf][3] = __float_as_uint(As[m0 + 8][k8 + tg + 4]);
            }
            #pragma unroll
            for (int nf = 0; nf < 4; nf++) {
                int n0 = wn * 32 + nf * 8 + g;
                bfr[nf][0] = __float_as_uint(Ks[n0][kb + k8 + tg]);
                bfr[nf][1] = __float_as_uint(Ks[n0][kb + k8 + tg + 4]);
            }
            #pragma unroll
            for (int mf = 0; mf < 2; mf++)
                #pragma unroll
                for (int nf = 0; nf < 4; nf++)
                    mma8(acc[mf][nf], a[mf][0], a[mf][1], a[mf][2], a[mf][3],
                         bfr[nf][0], bfr[nf][1]);
        }
        __syncthreads();
    }

    #pragma unroll
    for (int mf = 0; mf < 2; mf++) {
        int rq = q0 + wm * 32 + mf * 16 + g;
        #pragma unroll
        for (int nf = 0; nf < 4; nf++) {
            int kk = n0base + wn * 32 + nf * 8 + tg * 2;
            float p0 = 10000.0f * (1.0f - (float)mask[b * SQ + kk]);
            float p1 = 10000.0f * (1.0f - (float)mask[b * SQ + kk + 1]);
            float v00 = acc[mf][nf][0] * 0.125f - p0;
            float v01 = acc[mf][nf][1] * 0.125f - p1;
            float v10 = acc[mf][nf][2] * 0.125f - p0;
            float v11 = acc[mf][nf][3] * 0.125f - p1;
            *(float2*)&Sc[((size_t)bh * SQ + rq) * SQ + kk] = make_float2(v00, v01);
            *(float2*)&Sc[((size_t)bh * SQ + rq + 8) * SQ + kk] = make_float2(v10, v11);
        }
    }
}

// ---------------- PV: out[b,s,h*64+dh] = P[b,h,s,:] @ V[b,h,:,dh] ----------------
__global__ __launch_bounds__(256) void pv_tf32(
    const float* __restrict__ P, const float* __restrict__ V,
    float* __restrict__ out)
{
    __shared__ float As[128][36];
    __shared__ float Bs[32][72];

    const int tid = threadIdx.x;
    const int lane = tid & 31, warp = tid >> 5;
    const int wm = warp >> 1, wn = warp & 1;
    const int g = lane >> 2, tg = lane & 3;

    const int bh = blockIdx.x;
    const int s0 = blockIdx.y * 128;
    const int b = bh / H, hh = bh % H;

    const float* Pp = P + ((size_t)bh * SQ + s0) * SQ;
    const float* Vp = V + (size_t)bh * SQ * DH;

    float acc[2][4][4] = {};

    for (int k0 = 0; k0 < SQ; k0 += 32) {
        #pragma unroll
        for (int i = 0; i < 4; i++) {
            int f = tid + 256 * i;
            int r = f >> 3, c4 = (f & 7) << 2;
            float4 v = *(const float4*)&Pp[(size_t)r * SQ + k0 + c4];
            float4 t;
            t.x = to_tf32(v.x); t.y = to_tf32(v.y);
            t.z = to_tf32(v.z); t.w = to_tf32(v.w);
            *(float4*)&As[r][c4] = t;
        }
        #pragma unroll
        for (int i = 0; i < 2; i++) {
            int f = tid + 256 * i;
            int r = f >> 4, c4 = (f & 15) << 2;
            float4 v = *(const float4*)&Vp[(size_t)(k0 + r) * DH + c4];
            float4 t;
            t.x = to_tf32(v.x); t.y = to_tf32(v.y);
            t.z = to_tf32(v.z); t.w = to_tf32(v.w);
            *(float4*)&Bs[r][c4] = t;
        }
        __syncthreads();

        #pragma unroll
        for (int ks = 0; ks < 4; ks++) {
            const int k8 = ks * 8;
            uint32_t a[2][4], bfr[4][2];
            #pragma unroll
            for (int mf = 0; mf < 2; mf++) {
                int m0 = wm * 32 + mf * 16 + g;
                a[mf][0] = __float_as_uint(As[m0][k8 + tg]);
                a[mf][1] = __float_as_uint(As[m0 + 8][k8 + tg]);
                a[mf][2] = __float_as_uint(As[m0][k8 + tg + 4]);
                a[mf][3] = __float_as_uint(As[m0 + 8][k8 + tg + 4]);
            }
            #pragma unroll
            for (int nf = 0; nf < 4; nf++) {
                int n0 = wn * 32 + nf * 8 + g;
                bfr[nf][0] = __float_as_uint(Bs[k8 + tg][n0]);
                bfr[nf][1] = __float_as_uint(Bs[k8 + tg + 4][n0]);
            }
            #pragma unroll
            for (int mf = 0; mf < 2; mf++)
                #pragma unroll
                for (int nf = 0; nf < 4; nf++)
                    mma8(acc[mf][nf], a[mf][0], a[mf][1], a[mf][2], a[mf][3],
                         bfr[nf][0], bfr[nf][1]);
        }
        __syncthreads();
    }

    #pragma unroll
    for (int mf = 0; mf < 2; mf++) {
        int s = s0 + wm * 32 + mf * 16 + g;
        #pragma unroll
        for (int nf = 0; nf < 4; nf++) {
            int c = hh * DH + wn * 32 + nf * 8 + tg * 2;
            *(float2*)&out[((size_t)b * SQ + s) * D + c] =
                make_float2(acc[mf][nf][0], acc[mf][nf][1]);
            *(float2*)&out[((size_t)b * SQ + s + 8) * D + c] =
                make_float2(acc[mf][nf][2], acc[mf][nf][3]);
        }
    }
}

// ---------------- softmax over last dim (256), one warp per row ----------------
__global__ __launch_bounds__(256) void softmax_kernel(float* __restrict__ Sc)
{
    const int row = blockIdx.x * 8 + (threadIdx.x >> 5);
    const int lane = threadIdx.x & 31;
    float* p = Sc + (size_t)row * SQ + lane * 8;

    float v[8];
    *(float4*)&v[0] = *(float4*)p;
    *(float4*)&v[4] = *(float4*)(p + 4);

    float m = v[0];
    #pragma unroll
    for (int j = 1; j < 8; j++) m = fmaxf(m, v[j]);
    #pragma unroll
    for (int o = 16; o; o >>= 1) m = fmaxf(m, __shfl_xor_sync(0xffffffffu, m, o));

    float s = 0.0f;
    #pragma unroll
    for (int j = 0; j < 8; j++) { v[j] = expf(v[j] - m); s += v[j]; }
    #pragma unroll
    for (int o = 16; o; o >>= 1) s += __shfl_xor_sync(0xffffffffu, s, o);

    float inv = 1.0f / s;
    #pragma unroll
    for (int j = 0; j < 8; j++) v[j] *= inv;

    *(float4*)p = *(float4*)&v[0];
    *(float4*)(p + 4) = *(float4*)&v[4];
}

// ---------------- residual add + LayerNorm (in-place on x) ----------------
__global__ __launch_bounds__(256) void addln_kernel(
    float* __restrict__ x, const float* __restrict__ hbuf,
    const float* __restrict__ g, const float* __restrict__ bta)
{
    __shared__ float red[256];
    const int row = blockIdx.x;
    const size_t base = (size_t)row * D;
    const int t = threadIdx.x;

    float v0 = x[base + t]       + hbuf[base + t];
    float v1 = x[base + t + 256] + hbuf[base + t + 256];
    float v2 = x[base + t + 512] + hbuf[base + t + 512];

    red[t] = v0 + v1 + v2;
    __syncthreads();
    for (int o = 128; o; o >>= 1) { if (t < o) red[t] += red[t + o]; __syncthreads(); }
    float mean = red[0] * (1.0f / 768.0f);
    __syncthreads();

    float d0 = v0 - mean, d1 = v1 - mean, d2 = v2 - mean;
    red[t] = d0 * d0 + d1 * d1 + d2 * d2;
    __syncthreads();
    for (int o = 128; o; o >>= 1) { if (t < o) red[t] += red[t + o]; __syncthreads(); }
    float inv = rsqrtf(red[0] * (1.0f / 768.0f) + 1e-12f);

    x[base + t]       = d0 * inv * g[t]       + bta[t];
    x[base + t + 256] = d1 * inv * g[t + 256] + bta[t + 256];
    x[base + t + 512] = d2 * inv * g[t + 512] + bta[t + 512];
}

// ---------------- host orchestration ----------------
static float *gx, *gy, *gqkv, *gsc, *gh, *gffn;
static bool g_resolved = false;

#define SMEM128 ((2*128*36 + 2*32*136) * (int)sizeof(float))  // 71680
#define SMEM64  ((2*128*36 + 2*32*72)  * (int)sizeof(float))  // 55296

static void resolve_symbols() {
    if (g_resolved) return;
    cudaGetSymbolAddress((void**)&gx,   g_x);
    cudaGetSymbolAddress((void**)&gy,   g_y);
    cudaGetSymbolAddress((void**)&gqkv, g_qkv);
    cudaGetSymbolAddress((void**)&gsc,  g_sc);
    cudaGetSymbolAddress((void**)&gh,   g_h);
    cudaGetSymbolAddress((void**)&gffn, g_ffn);
    cudaFuncSetAttribute(gemm_db<128,2>, cudaFuncAttributeMaxDynamicSharedMemorySize, SMEM128);
    cudaFuncSetAttribute(gemm_db<128,1>, cudaFuncAttributeMaxDynamicSharedMemorySize, SMEM128);
    cudaFuncSetAttribute(gemm_db<64,0>,  cudaFuncAttributeMaxDynamicSharedMemorySize, SMEM64);
    g_resolved = true;
}

static void run_mhsa(const float* qin, const float* kvin,
                     const float* Wp, const float* bp, const int* mask,
                     float* stream_buf, const float* lng, const float* lnb)
{
    // fused QKV: 3 matrices x 6 col-blocks x 16 row-blocks = 288 blocks
    gemm_db<128,2><<<dim3(18, 16), 256, SMEM128>>>(qin, kvin, Wp, bp, gqkv, D, D);
    scores_tf32<<<dim3(BB * H, SQ / 128, SQ / 64), 256>>>(gqkv, gqkv + MD, mask, gsc);
    softmax_kernel<<<BB * H * SQ / 8, 256>>>(gsc);
    pv_tf32<<<dim3(BB * H, SQ / 128), 256>>>(gsc, gqkv + 2 * MD, gh);
    addln_kernel<<<M, 256>>>(stream_buf, gh, lng, lnb);
}

static void run_ffn(float* buf, const float* w1, const float* b1,
                    const float* w2, const float* b2,
                    const float* lng, const float* lnb)
{
    gemm_db<128,1><<<dim3(FF / 128, 16), 256, SMEM128>>>(buf, buf, w1, b1, gffn, FF, D);
    gemm_db<64,0><<<dim3(D / 64, 16), 256, SMEM64>>>(gffn, gffn, w2, b2, gh, D, FF);
    addln_kernel<<<M, 256>>>(buf, gh, lng, lnb);
}

extern "C" void kernel_launch(void* const* d_in, const int* in_sizes, int n_in,
                              void* d_out, int out_size)
{
    const float* x     = (const float*)d_in[0];
    const float* y     = (const float*)d_in[1];
    const int*   xmask = (const int*)  d_in[2];
    const int*   ymask = (const int*)  d_in[3];
    const float* ax_w  = (const float*)d_in[4];
    const float* ax_b  = (const float*)d_in[5];
    const float* cx_w  = (const float*)d_in[6];
    const float* cx_b  = (const float*)d_in[7];
    const float* fx_w1 = (const float*)d_in[8];
    const float* fx_b1 = (const float*)d_in[9];
    const float* fx_w2 = (const float*)d_in[10];
    const float* fx_b2 = (const float*)d_in[11];
    const float* ay_w  = (const float*)d_in[12];
    const float* ay_b  = (const float*)d_in[13];
    const float* cy_w  = (const float*)d_in[14];
    const float* cy_b  = (const float*)d_in[15];
    const float* fy_w1 = (const float*)d_in[16];
    const float* fy_b1 = (const float*)d_in[17];
    const float* fy_w2 = (const float*)d_in[18];
    const float* fy_b2 = (const float*)d_in[19];
    const float* lnx_g = (const float*)d_in[20];
    const float* lnx_b = (const float*)d_in[21];
    const float* lny_g = (const float*)d_in[22];
    const float* lny_b = (const float*)d_in[23];

    resolve_symbols();

    cudaMemcpyAsync(gx, x, MD * sizeof(float), cudaMemcpyDeviceToDevice, 0);
    cudaMemcpyAsync(gy, y, MD * sizeof(float), cudaMemcpyDeviceToDevice, 0);

    for (int l = 0; l < 6; l++) {
        const float* axw = ax_w + (size_t)l * 3 * D * D;
        const float* axb = ax_b + (size_t)l * 3 * D;
        const float* ayw = ay_w + (size_t)l * 3 * D * D;
        const float* ayb = ay_b + (size_t)l * 3 * D;
        const float* cxw = cx_w + (size_t)l * 3 * D * D;
        const float* cxb = cx_b + (size_t)l * 3 * D;
        const float* cyw = cy_w + (size_t)l * 3 * D * D;
        const float* cyb = cy_b + (size_t)l * 3 * D;
        const float* fxw1 = fx_w1 + (size_t)l * D * FF;
        const float* fxb1 = fx_b1 + (size_t)l * FF;
        const float* fxw2 = fx_w2 + (size_t)l * FF * D;
        const float* fxb2 = fx_b2 + (size_t)l * D;
        const float* fyw1 = fy_w1 + (size_t)l * D * FF;
        const float* fyb1 = fy_b1 + (size_t)l * FF;
        const float* fyw2 = fy_w2 + (size_t)l * FF * D;
        const float* fyb2 = fy_b2 + (size_t)l * D;

        run_mhsa(gx, gx, axw, axb, xmask, gx, lnx_g + 0 * D, lnx_b + 0 * D);
        run_mhsa(gy, gy, ayw, ayb, ymask, gy, lny_g + 0 * D, lny_b + 0 * D);
        run_mhsa(gx, gy, cxw, cxb, ymask, gx, lnx_g + 1 * D, lnx_b + 1 * D);
        run_mhsa(gy, gx, cyw, cyb, xmask, gy, lny_g + 1 * D, lny_b + 1 * D);
        run_ffn(gx, fxw1, fxb1, fxw2, fxb2, lnx_g + 2 * D, lnx_b + 2 * D);
        run_ffn(gy, fyw1, fyb1, fyw2, fyb2, lny_g + 2 * D, lny_b + 2 * D);
    }

    cudaMemcpyAsync((float*)d_out,      gx, MD * sizeof(float), cudaMemcpyDeviceToDevice, 0);
    cudaMemcpyAsync((float*)d_out + MD, gy, MD * sizeof(float), cudaMemcpyDeviceToDevice, 0);
}